// round 10
// baseline (speedup 1.0000x reference)
#include <cuda_runtime.h>
#include <stdint.h>
#include <math.h>

#define B_SAMP 8192
#define K_DIM  7056
#define KPAD2  7168          // 56 * 128
#define N1     512
#define FEAT   256
#define NQ     8
#define NL     3

#define KC2   128
#define NCH   (KPAD2 / KC2)  // 56
#define ABYT  16384          // 128 rows x 128 B
#define BUF2  (4 * ABYT)     // Aq1|Aq2|Bq1|Bq2
#define GSMEM2 (2 * BUF2)    // 128 KB

// ---------------- device scratch ----------------
__device__ float g_h[(size_t)B_SAMP * N1];
__device__ float g_gate[NL * NQ * 8];     // fused U = Rz*Ry*Rx per (l,q)
__device__ signed char g_xq1[(size_t)B_SAMP * KPAD2];
__device__ signed char g_xq2[(size_t)B_SAMP * KPAD2];
__device__ signed char g_wq1[(size_t)N1 * KPAD2];
__device__ signed char g_wq2[(size_t)N1 * KPAD2];
__device__ float g_xs[B_SAMP];
__device__ float g_wS[N1];
__device__ int   g_wsmax[N1];

// ---------------- helpers ----------------
__device__ __forceinline__ uint32_t smem_u32(const void* p) {
    uint32_t a;
    asm("{ .reg .u64 t; cvta.to.shared.u64 t, %1; cvt.u32.u64 %0, t; }"
        : "=r"(a) : "l"(p));
    return a;
}
__device__ __forceinline__ void cpasync16(uint32_t dst, const void* src) {
    asm volatile("cp.async.cg.shared.global [%0], [%1], 16;"
                 :: "r"(dst), "l"(src) : "memory");
}
__device__ __forceinline__ void cp_commit() {
    asm volatile("cp.async.commit_group;" ::: "memory");
}
__device__ __forceinline__ void cp_wait1() {
    asm volatile("cp.async.wait_group 1;" ::: "memory");
}
__device__ __forceinline__ void cp_wait0() {
    asm volatile("cp.async.wait_group 0;" ::: "memory");
}
__device__ __forceinline__ void ldsm4(uint32_t* r, uint32_t addr) {
    asm volatile("ldmatrix.sync.aligned.m8n8.x4.shared.b16 {%0,%1,%2,%3}, [%4];"
                 : "=r"(r[0]), "=r"(r[1]), "=r"(r[2]), "=r"(r[3]) : "r"(addr));
}
__device__ __forceinline__ void imma(int* d, const uint32_t* a,
                                     uint32_t b0, uint32_t b1) {
    asm volatile(
        "mma.sync.aligned.m16n8k32.row.col.s32.s8.s8.s32 "
        "{%0,%1,%2,%3},{%4,%5,%6,%7},{%8,%9},{%0,%1,%2,%3};"
        : "+r"(d[0]), "+r"(d[1]), "+r"(d[2]), "+r"(d[3])
        : "r"(a[0]), "r"(a[1]), "r"(a[2]), "r"(a[3]), "r"(b0), "r"(b1));
}
__device__ __forceinline__ uint32_t swz(uint32_t off) {   // 128B rows
    return off ^ (((off >> 7) & 7) << 4);
}
__device__ __forceinline__ uint32_t pack4(int a, int b, int c, int d) {
    return (a & 0xFF) | ((b & 0xFF) << 8) | ((c & 0xFF) << 16) | ((d & 0xFF) << 24);
}

// ---------------------------------------------------------------------------
// Fused gate precompute: U = Rz(z)*Ry(y)*Rx(x) as complex 2x2 per (l,q)
// ---------------------------------------------------------------------------
__global__ void prep_gates_kernel(const float* __restrict__ qp) {
    int p = threadIdx.x;
    if (p < NL * NQ) {
        float cx, sx, cy, sy, cz, sz;
        sincosf(0.5f * qp[p * 3 + 0], &sx, &cx);
        sincosf(0.5f * qp[p * 3 + 1], &sy, &cy);
        sincosf(0.5f * qp[p * 3 + 2], &sz, &cz);
        // m = Ry*Rx
        const float m00r = cy * cx, m00i =  sy * sx;
        const float m01r = -sy * cx, m01i = -cy * sx;
        const float m10r =  sy * cx, m10i = -cy * sx;
        const float m11r =  cy * cx, m11i = -sy * sx;
        // row0 *= (cz - i sz); row1 *= (cz + i sz)
        float* g = g_gate + p * 8;
        g[0] = cz * m00r + sz * m00i;  g[1] = cz * m00i - sz * m00r;
        g[2] = cz * m01r + sz * m01i;  g[3] = cz * m01i - sz * m01r;
        g[4] = cz * m10r - sz * m10i;  g[5] = cz * m10i + sz * m10r;
        g[6] = cz * m11r - sz * m11i;  g[7] = cz * m11i + sz * m11r;
    }
}

// ---------------------------------------------------------------------------
// W column-max (atomicMax on float bits; idempotent across graph replays)
// ---------------------------------------------------------------------------
__global__ void wmax_kernel(const float* __restrict__ W) {
    __shared__ int smax[N1];
    for (int i = threadIdx.x; i < N1; i += blockDim.x) smax[i] = 0;
    __syncthreads();
    const int total = K_DIM * N1;
    for (int idx = blockIdx.x * blockDim.x + threadIdx.x; idx < total;
         idx += gridDim.x * blockDim.x) {
        const int n = idx & (N1 - 1);
        atomicMax(&smax[n], __float_as_int(fabsf(W[idx])));
    }
    __syncthreads();
    for (int i = threadIdx.x; i < N1; i += blockDim.x)
        atomicMax(&g_wsmax[i], smax[i]);
}

__global__ void wfin_kernel() {
    const int n = threadIdx.x;
    if (n < N1) {
        const float m = fmaxf(__int_as_float(g_wsmax[n]), 1e-30f);
        g_wS[n] = m * (1.0f / 127.0f);
    }
}

// ---------------------------------------------------------------------------
// W quantize + transpose: g_wq1/2[n][k] int8, K-major, zero-padded
// ---------------------------------------------------------------------------
__global__ void wquant_kernel(const float* __restrict__ W) {
    __shared__ float tile[32][33];
    const int k0 = blockIdx.x * 32;
    const int n0 = blockIdx.y * 32;
    const int tx = threadIdx.x, ty = threadIdx.y;  // 32 x 8
    #pragma unroll
    for (int i = 0; i < 4; i++) {
        const int k = k0 + ty + i * 8;
        tile[ty + i * 8][tx] = (k < K_DIM) ? W[(size_t)k * N1 + n0 + tx] : 0.0f;
    }
    __syncthreads();
    #pragma unroll
    for (int i = 0; i < 4; i++) {
        const int n = n0 + ty + i * 8;
        const float S = g_wS[n];
        const float inv = 1.0f / S;
        const float v = tile[tx][ty + i * 8];
        const int q1 = __float2int_rn(v * inv);
        const float r = v - (float)q1 * S;
        const int q2 = __float2int_rn(r * inv * 254.0f);
        g_wq1[(size_t)n * KPAD2 + k0 + tx] = (signed char)q1;
        g_wq2[(size_t)n * KPAD2 + k0 + tx] = (signed char)q2;
    }
}

// ---------------------------------------------------------------------------
// X quantize: one block per row; row-max + 2-term int8 quant, single pass
// ---------------------------------------------------------------------------
__global__ __launch_bounds__(256) void xquant_kernel(const float* __restrict__ X) {
    __shared__ float srow[KPAD2];
    __shared__ float red[8];
    __shared__ float sbc;
    const int m = blockIdx.x;
    const int tid = threadIdx.x;
    const float4* src = (const float4*)(X + (size_t)m * K_DIM);
    float4* dst4 = (float4*)srow;

    float vmax = 0.0f;
    for (int i = tid; i < KPAD2 / 4; i += 256) {
        float4 v = (i < K_DIM / 4) ? src[i] : make_float4(0.f, 0.f, 0.f, 0.f);
        dst4[i] = v;
        vmax = fmaxf(vmax, fmaxf(fmaxf(fabsf(v.x), fabsf(v.y)),
                                 fmaxf(fabsf(v.z), fabsf(v.w))));
    }
    #pragma unroll
    for (int o = 16; o > 0; o >>= 1)
        vmax = fmaxf(vmax, __shfl_xor_sync(~0u, vmax, o));
    if ((tid & 31) == 0) red[tid >> 5] = vmax;
    __syncthreads();
    if (tid == 0) {
        float t = red[0];
        #pragma unroll
        for (int i = 1; i < 8; i++) t = fmaxf(t, red[i]);
        sbc = fmaxf(t, 1e-30f) * (1.0f / 127.0f);
        g_xs[m] = sbc;
    }
    __syncthreads();
    const float s = sbc;
    const float inv = 1.0f / s;

    uint32_t* q1o = (uint32_t*)(g_xq1 + (size_t)m * KPAD2);
    uint32_t* q2o = (uint32_t*)(g_xq2 + (size_t)m * KPAD2);
    for (int i = tid; i < KPAD2 / 4; i += 256) {
        const float4 v = dst4[i];
        const int a1 = __float2int_rn(v.x * inv);
        const int b1 = __float2int_rn(v.y * inv);
        const int c1 = __float2int_rn(v.z * inv);
        const int d1 = __float2int_rn(v.w * inv);
        const int a2 = __float2int_rn((v.x - (float)a1 * s) * inv * 254.0f);
        const int b2 = __float2int_rn((v.y - (float)b1 * s) * inv * 254.0f);
        const int c2 = __float2int_rn((v.z - (float)c1 * s) * inv * 254.0f);
        const int d2 = __float2int_rn((v.w - (float)d1 * s) * inv * 254.0f);
        q1o[i] = pack4(a1, b1, c1, d1);
        q2o[i] = pack4(a2, b2, c2, d2);
    }
}

// ---------------------------------------------------------------------------
// GEMM1 via IMMA s8: h = relu(dequant(xq @ wq^T) + b1)
// CTA 128x128, KC=128, 512 threads (16 warps, 4m x 4n), warp tile 32x32
// ---------------------------------------------------------------------------
__global__ __launch_bounds__(512, 1)
void gemm1_imma_kernel(const float* __restrict__ bias)
{
    extern __shared__ char smraw[];
    const uint32_t sb = smem_u32(smraw);

    const int tid  = threadIdx.x;
    const int lane = tid & 31;
    const int wid  = tid >> 5;
    const int wm   = wid >> 2;       // 0..3 -> m offset 32*wm
    const int wn   = wid & 3;        // 0..3 -> n offset 32*wn
    const int m0   = blockIdx.y * 128;
    const int n0   = blockIdx.x * 128;

    // cp.async geometry: j<2: idx = tid + 512*j; row = idx>>3; g = idx&7
    const int r0_ = tid >> 3, g0_ = tid & 7;
    const int r1_ = (tid + 512) >> 3, g1_ = (tid + 512) & 7;
    const uint32_t d0 = swz(r0_ * 128 + g0_ * 16);
    const uint32_t d1 = swz(r1_ * 128 + g1_ * 16);

    #define ISSUE(kb, buf) do {                                                \
        const uint32_t bo = sb + (buf) * BUF2;                                 \
        const size_t a0s = (size_t)(m0 + r0_) * KPAD2 + (kb) + g0_ * 16;       \
        const size_t a1s = (size_t)(m0 + r1_) * KPAD2 + (kb) + g1_ * 16;       \
        const size_t b0s = (size_t)(n0 + r0_) * KPAD2 + (kb) + g0_ * 16;       \
        const size_t b1s = (size_t)(n0 + r1_) * KPAD2 + (kb) + g1_ * 16;       \
        cpasync16(bo + d0,            g_xq1 + a0s);                            \
        cpasync16(bo + d1,            g_xq1 + a1s);                            \
        cpasync16(bo + ABYT + d0,     g_xq2 + a0s);                            \
        cpasync16(bo + ABYT + d1,     g_xq2 + a1s);                            \
        cpasync16(bo + 2 * ABYT + d0, g_wq1 + b0s);                            \
        cpasync16(bo + 2 * ABYT + d1, g_wq1 + b1s);                            \
        cpasync16(bo + 3 * ABYT + d0, g_wq2 + b0s);                            \
        cpasync16(bo + 3 * ABYT + d1, g_wq2 + b1s);                            \
        cp_commit();                                                           \
    } while (0)

    int accM[2][4][4], accC[2][4][4];
    #pragma unroll
    for (int i = 0; i < 2; i++)
        #pragma unroll
        for (int j = 0; j < 4; j++)
            #pragma unroll
            for (int c = 0; c < 4; c++) { accM[i][j][c] = 0; accC[i][j][c] = 0; }

    // ldsm lane addressing
    const int arow = lane & 15;                 // A: rows 0-15
    const int akoff = (lane >> 4) * 16;         // A: k byte offset 0/16
    const int brow = (lane & 7) + ((lane >> 4) << 3);  // B: n row
    const int bkoff = ((lane >> 3) & 1) * 16;          // B: k byte offset

    ISSUE(0, 0);

    for (int t = 0; t < NCH; t++) {
        const int buf = t & 1;
        if (t + 1 < NCH) { ISSUE((t + 1) * KC2, buf ^ 1); cp_wait1(); }
        else cp_wait0();
        __syncthreads();

        const uint32_t ab = sb + buf * BUF2;
        const uint32_t bb = ab + 2 * ABYT;

        #pragma unroll
        for (int ks = 0; ks < 4; ks++) {
            uint32_t a1[2][4], a2[2][4], b1[2][4], b2[2][4];
            #pragma unroll
            for (int mt = 0; mt < 2; mt++) {
                const uint32_t ad = ab + swz((wm * 32 + mt * 16 + arow) * 128
                                             + ks * 32 + akoff);
                ldsm4(a1[mt], ad);
                ldsm4(a2[mt], ad + ABYT);
            }
            #pragma unroll
            for (int p = 0; p < 2; p++) {
                const uint32_t bd = bb + swz((wn * 32 + p * 16 + brow) * 128
                                             + ks * 32 + bkoff);
                ldsm4(b1[p], bd);
                ldsm4(b2[p], bd + ABYT);
            }
            #pragma unroll
            for (int mt = 0; mt < 2; mt++)
                #pragma unroll
                for (int p = 0; p < 2; p++)
                    #pragma unroll
                    for (int h = 0; h < 2; h++) {
                        const int nt = p * 2 + h;
                        imma(accM[mt][nt], a1[mt], b1[p][2 * h], b1[p][2 * h + 1]);
                        imma(accC[mt][nt], a1[mt], b2[p][2 * h], b2[p][2 * h + 1]);
                        imma(accC[mt][nt], a2[mt], b1[p][2 * h], b1[p][2 * h + 1]);
                    }
        }
        __syncthreads();
    }

    // epilogue: dequant (double for exact s32->fp), bias + relu
    const int fr = lane >> 2;
    const int fc = (lane & 3) * 2;
    #pragma unroll
    for (int nt = 0; nt < 4; nt++) {
        const int c = n0 + wn * 32 + nt * 8 + fc;
        const double S0 = (double)g_wS[c], S1 = (double)g_wS[c + 1];
        const float bb0 = bias[c], bb1 = bias[c + 1];
        #pragma unroll
        for (int mt = 0; mt < 2; mt++) {
            const int r = m0 + wm * 32 + mt * 16 + fr;
            const double sa = (double)g_xs[r];
            const double sc = (double)g_xs[r + 8];
            const int* M = accM[mt][nt];
            const int* C = accC[mt][nt];
            float2 o0, o1;
            o0.x = fmaxf((float)(sa * S0 * ((double)M[0] + (double)C[0] * (1.0 / 254.0))) + bb0, 0.f);
            o0.y = fmaxf((float)(sa * S1 * ((double)M[1] + (double)C[1] * (1.0 / 254.0))) + bb1, 0.f);
            o1.x = fmaxf((float)(sc * S0 * ((double)M[2] + (double)C[2] * (1.0 / 254.0))) + bb0, 0.f);
            o1.y = fmaxf((float)(sc * S1 * ((double)M[3] + (double)C[3] * (1.0 / 254.0))) + bb1, 0.f);
            *(float2*)&g_h[(size_t)r * N1 + c] = o0;
            *(float2*)&g_h[(size_t)(r + 8) * N1 + c] = o1;
        }
    }
    #undef ISSUE
}

// ---------------------------------------------------------------------------
// Fused tail: angles -> 8-qubit sim (fused U gates) -> post-MLP
// ---------------------------------------------------------------------------
__device__ __forceinline__ float bsum(float v) {
    #pragma unroll
    for (int m = 16; m > 0; m >>= 1) v += __shfl_xor_sync(0xffffffffu, v, m);
    return v;
}

__global__ __launch_bounds__(256) void tail_kernel(
    const float* __restrict__ preW2, const float* __restrict__ preb2,
    const float* __restrict__ pW1, const float* __restrict__ pb1,
    const float* __restrict__ pW2, const float* __restrict__ pb2,
    const float* __restrict__ pW3, const float* __restrict__ pb3,
    float* __restrict__ out)
{
    __shared__ float sh[8][128];
    __shared__ float w2s[128 * 64];

    const int lane = threadIdx.x & 31;
    const int w    = threadIdx.x >> 5;
    const int sample = blockIdx.x * 8 + w;

    for (int i = threadIdx.x; i < (128 * 64) / 4; i += 256)
        ((float4*)w2s)[i] = ((const float4*)pW2)[i];
    __syncthreads();

    const float* hrow = g_h + (size_t)sample * N1;
    float acc[8] = {0, 0, 0, 0, 0, 0, 0, 0};
    #pragma unroll
    for (int t = 0; t < 16; t++) {
        const int k = t * 32 + lane;
        const float hv = hrow[k];
        const float4 wa = *(const float4*)(preW2 + (size_t)k * FEAT);
        const float4 wb = *(const float4*)(preW2 + (size_t)k * FEAT + 4);
        acc[0] = fmaf(hv, wa.x, acc[0]); acc[1] = fmaf(hv, wa.y, acc[1]);
        acc[2] = fmaf(hv, wa.z, acc[2]); acc[3] = fmaf(hv, wa.w, acc[3]);
        acc[4] = fmaf(hv, wb.x, acc[4]); acc[5] = fmaf(hv, wb.y, acc[5]);
        acc[6] = fmaf(hv, wb.z, acc[6]); acc[7] = fmaf(hv, wb.w, acc[7]);
    }

    float v0[8], v1[8];
    #pragma unroll
    for (int q = 0; q < 8; q++) {
        const float s_ = bsum(acc[q]);
        const float th = tanhf(s_ + preb2[q]) * 1.57079632679f;
        float c, s;
        sincosf(th, &s, &c);
        v0[q] = (c - s) * 0.70710678118f;
        v1[q] = (c + s) * 0.70710678118f;
    }
    float re[8], im[8];
    #pragma unroll
    for (int j = 0; j < 8; j++) {
        const int g = (lane << 3) | j;
        float a = 1.0f;
        #pragma unroll
        for (int q = 0; q < 8; q++)
            a *= ((g >> (7 - q)) & 1) ? v1[q] : v0[q];
        re[j] = a; im[j] = 0.0f;
    }

    for (int l = 0; l < NL; l++) {
        // CNOT(0,1)
        {
            const int take = (lane >> 4) & 1;
            #pragma unroll
            for (int j = 0; j < 8; j++) {
                const float orr = __shfl_xor_sync(~0u, re[j], 8);
                const float oii = __shfl_xor_sync(~0u, im[j], 8);
                if (take) { re[j] = orr; im[j] = oii; }
            }
        }
        // CNOT(2,3)
        {
            const int take = (lane >> 2) & 1;
            #pragma unroll
            for (int j = 0; j < 8; j++) {
                const float orr = __shfl_xor_sync(~0u, re[j], 2);
                const float oii = __shfl_xor_sync(~0u, im[j], 2);
                if (take) { re[j] = orr; im[j] = oii; }
            }
        }
        // CNOT(4,5)
        if (lane & 1) {
            #pragma unroll
            for (int j = 0; j < 4; j++) {
                float t = re[j]; re[j] = re[j + 4]; re[j + 4] = t;
                t = im[j]; im[j] = im[j + 4]; im[j + 4] = t;
            }
        }
        // CNOT(6,7)
        {
            float t;
            t = re[2]; re[2] = re[3]; re[3] = t;  t = im[2]; im[2] = im[3]; im[3] = t;
            t = re[6]; re[6] = re[7]; re[7] = t;  t = im[6]; im[6] = im[7]; im[7] = t;
        }
        // CNOT(1,2)
        {
            const int take = (lane >> 3) & 1;
            #pragma unroll
            for (int j = 0; j < 8; j++) {
                const float orr = __shfl_xor_sync(~0u, re[j], 4);
                const float oii = __shfl_xor_sync(~0u, im[j], 4);
                if (take) { re[j] = orr; im[j] = oii; }
            }
        }
        // CNOT(3,4)
        {
            const int take = (lane >> 1) & 1;
            #pragma unroll
            for (int j = 0; j < 8; j++) {
                const float orr = __shfl_xor_sync(~0u, re[j], 1);
                const float oii = __shfl_xor_sync(~0u, im[j], 1);
                if (take) { re[j] = orr; im[j] = oii; }
            }
        }
        // CNOT(5,6)
        {
            float t;
            t = re[4]; re[4] = re[6]; re[6] = t;  t = im[4]; im[4] = im[6]; im[6] = t;
            t = re[5]; re[5] = re[7]; re[7] = t;  t = im[5]; im[5] = im[7]; im[7] = t;
        }

        // fused U = Rz*Ry*Rx per qubit
        #pragma unroll
        for (int q = 0; q < 8; q++) {
            const float* gg = g_gate + (l * 8 + q) * 8;
            if (q < 5) {
                const int M = 1 << (4 - q);
                const int bit = (lane >> (4 - q)) & 1;
                const float uar = bit ? gg[4] : gg[0];
                const float uai = bit ? gg[5] : gg[1];
                const float ubr = bit ? gg[6] : gg[2];
                const float ubi = bit ? gg[7] : gg[3];
                #pragma unroll
                for (int j = 0; j < 8; j++) {
                    const float orr = __shfl_xor_sync(~0u, re[j], M);
                    const float oii = __shfl_xor_sync(~0u, im[j], M);
                    const float a0r = bit ? orr : re[j];
                    const float a0i = bit ? oii : im[j];
                    const float a1r = bit ? re[j] : orr;
                    const float a1i = bit ? im[j] : oii;
                    re[j] = uar * a0r - uai * a0i + ubr * a1r - ubi * a1i;
                    im[j] = uar * a0i + uai * a0r + ubr * a1i + ubi * a1r;
                }
            } else {
                const int S = 1 << (7 - q); // 4, 2, 1
                const float u00r = gg[0], u00i = gg[1], u01r = gg[2], u01i = gg[3];
                const float u10r = gg[4], u10i = gg[5], u11r = gg[6], u11i = gg[7];
                #pragma unroll
                for (int j0 = 0; j0 < 8; j0++) {
                    if (j0 & S) continue;
                    const int j1 = j0 + S;
                    const float r0 = re[j0], i0 = im[j0];
                    const float r1 = re[j1], i1 = im[j1];
                    re[j0] = u00r * r0 - u00i * i0 + u01r * r1 - u01i * i1;
                    im[j0] = u00r * i0 + u00i * r0 + u01r * i1 + u01i * r1;
                    re[j1] = u10r * r0 - u10i * i0 + u11r * r1 - u11i * i1;
                    im[j1] = u10r * i0 + u10i * r0 + u11r * i1 + u11i * r1;
                }
            }
        }
    }

    float ev[8] = {0, 0, 0, 0, 0, 0, 0, 0};
    #pragma unroll
    for (int j = 0; j < 8; j++) {
        const float p = re[j] * re[j] + im[j] * im[j];
        const int g = (lane << 3) | j;
        #pragma unroll
        for (int q = 0; q < 8; q++)
            ev[q] += ((g >> (7 - q)) & 1) ? -p : p;
    }
    #pragma unroll
    for (int q = 0; q < 8; q++) ev[q] = bsum(ev[q]);

    float* shw = sh[w];
    #pragma unroll
    for (int r = 0; r < 4; r++) {
        const int u = r * 32 + lane;
        float s_ = pb1[u];
        #pragma unroll
        for (int q = 0; q < 8; q++)
            s_ = fmaf(ev[q], pW1[q * 128 + u], s_);
        shw[u] = fmaxf(s_, 0.0f);
    }
    __syncwarp();

    float s0 = pb2[2 * lane], s1 = pb2[2 * lane + 1];
    #pragma unroll 4
    for (int u = 0; u < 128; u++) {
        const float hu = shw[u];
        const float2 wv = *(const float2*)&w2s[u * 64 + 2 * lane];
        s0 = fmaf(hu, wv.x, s0);
        s1 = fmaf(hu, wv.y, s1);
    }
    const float h3a = fmaxf(s0, 0.0f);
    const float h3b = fmaxf(s1, 0.0f);
    __syncwarp();
    shw[2 * lane] = h3a;
    shw[2 * lane + 1] = h3b;
    __syncwarp();

    if (lane < 6) {
        float s_ = pb3[lane];
        #pragma unroll 8
        for (int v = 0; v < 64; v++)
            s_ = fmaf(shw[v], pW3[v * 6 + lane], s_);
        out[(size_t)sample * 6 + lane] = s_;
    }
}

// ---------------------------------------------------------------------------
extern "C" void kernel_launch(void* const* d_in, const int* in_sizes, int n_in,
                              void* d_out, int out_size)
{
    const float* x     = (const float*)d_in[0];
    const float* preW1 = (const float*)d_in[1];
    const float* preb1 = (const float*)d_in[2];
    const float* preW2 = (const float*)d_in[3];
    const float* preb2 = (const float*)d_in[4];
    const float* qp    = (const float*)d_in[5];
    const float* pW1   = (const float*)d_in[6];
    const float* pb1   = (const float*)d_in[7];
    const float* pW2   = (const float*)d_in[8];
    const float* pb2   = (const float*)d_in[9];
    const float* pW3   = (const float*)d_in[10];
    const float* pb3   = (const float*)d_in[11];
    float* out = (float*)d_out;

    cudaFuncSetAttribute(gemm1_imma_kernel,
                         cudaFuncAttributeMaxDynamicSharedMemorySize, GSMEM2);

    prep_gates_kernel<<<1, 32>>>(qp);
    wmax_kernel<<<148, 512>>>(preW1);
    wfin_kernel<<<1, N1>>>();
    wquant_kernel<<<dim3(KPAD2 / 32, N1 / 32), dim3(32, 8)>>>(preW1);
    xquant_kernel<<<B_SAMP, 256>>>(x);

    dim3 gg(N1 / 128, B_SAMP / 128);   // (4, 64)
    gemm1_imma_kernel<<<gg, 512, GSMEM2>>>(preb1);

    tail_kernel<<<B_SAMP / 8, 256>>>(preW2, preb2, pW1, pb1, pW2, pb2,
                                     pW3, pb3, out);
}

// round 14
// speedup vs baseline: 2.6969x; 2.6969x over previous
#include <cuda_runtime.h>
#include <cuda_bf16.h>
#include <stdint.h>
#include <math.h>

#define B_SAMP 8192
#define K_DIM  7056
#define KPAD   7104          // 111 * 64
#define N1     512
#define FEAT   256
#define NQ     8
#define NL     3

#define KC    64
#define NCH   (KPAD / KC)    // 111
#define ATILE 16384          // 128 rows x 128 B (64 bf16)
#define BUF   (4 * ATILE)    // Ah|Al|Bh|Bl
#define GSMEM (2 * BUF)      // 128 KB

// ---------------- device scratch ----------------
__device__ float g_h[(size_t)B_SAMP * N1];
__device__ float g_gate[NL * NQ * 8];                 // fused U = Rz*Ry*Rx
__device__ __nv_bfloat16 g_xh[(size_t)B_SAMP * KPAD];
__device__ __nv_bfloat16 g_xl[(size_t)B_SAMP * KPAD];
__device__ __nv_bfloat16 g_wth[(size_t)N1 * KPAD];    // W1^T hi (K-major)
__device__ __nv_bfloat16 g_wtl[(size_t)N1 * KPAD];

// ---------------- helpers ----------------
__device__ __forceinline__ uint32_t smem_u32(const void* p) {
    uint32_t a;
    asm("{ .reg .u64 t; cvta.to.shared.u64 t, %1; cvt.u32.u64 %0, t; }"
        : "=r"(a) : "l"(p));
    return a;
}
__device__ __forceinline__ void cpasync16(uint32_t dst, const void* src) {
    asm volatile("cp.async.cg.shared.global [%0], [%1], 16;"
                 :: "r"(dst), "l"(src) : "memory");
}
__device__ __forceinline__ void cp_commit() {
    asm volatile("cp.async.commit_group;" ::: "memory");
}
__device__ __forceinline__ void cp_wait1() {
    asm volatile("cp.async.wait_group 1;" ::: "memory");
}
__device__ __forceinline__ void cp_wait0() {
    asm volatile("cp.async.wait_group 0;" ::: "memory");
}
__device__ __forceinline__ void ldsm4(uint32_t* r, uint32_t addr) {
    asm volatile("ldmatrix.sync.aligned.m8n8.x4.shared.b16 {%0,%1,%2,%3}, [%4];"
                 : "=r"(r[0]), "=r"(r[1]), "=r"(r[2]), "=r"(r[3]) : "r"(addr));
}
__device__ __forceinline__ void mma_bf16(float* d, const uint32_t* a,
                                         uint32_t b0, uint32_t b1) {
    asm volatile(
        "mma.sync.aligned.m16n8k16.row.col.f32.bf16.bf16.f32 "
        "{%0,%1,%2,%3},{%4,%5,%6,%7},{%8,%9},{%0,%1,%2,%3};"
        : "+f"(d[0]), "+f"(d[1]), "+f"(d[2]), "+f"(d[3])
        : "r"(a[0]), "r"(a[1]), "r"(a[2]), "r"(a[3]), "r"(b0), "r"(b1));
}
__device__ __forceinline__ uint32_t swz(uint32_t off) {   // 128B rows
    return off ^ (((off >> 7) & 7) << 4);
}
// pack 2 floats (e0 -> low 16 bits) to bf16x2
__device__ __forceinline__ uint32_t packbf(float e0, float e1) {
    uint32_t r;
    asm("cvt.rn.bf16x2.f32 %0, %1, %2;" : "=r"(r) : "f"(e1), "f"(e0));
    return r;
}
__device__ __forceinline__ uint32_t packlo(uint32_t hpair, float e0, float e1) {
    float h0 = __uint_as_float(hpair << 16);
    float h1 = __uint_as_float(hpair & 0xFFFF0000u);
    return packbf(e0 - h0, e1 - h1);
}

// ---------------------------------------------------------------------------
// Fused gate precompute: U = Rz*Ry*Rx complex 2x2 per (layer,qubit)
// ---------------------------------------------------------------------------
__global__ void prep_gates_kernel(const float* __restrict__ qp) {
    int p = threadIdx.x;
    if (p < NL * NQ) {
        float cx, sx, cy, sy, cz, sz;
        sincosf(0.5f * qp[p * 3 + 0], &sx, &cx);
        sincosf(0.5f * qp[p * 3 + 1], &sy, &cy);
        sincosf(0.5f * qp[p * 3 + 2], &sz, &cz);
        const float m00r = cy * cx, m00i =  sy * sx;
        const float m01r = -sy * cx, m01i = -cy * sx;
        const float m10r =  sy * cx, m10i = -cy * sx;
        const float m11r =  cy * cx, m11i = -sy * sx;
        float* g = g_gate + p * 8;
        g[0] = cz * m00r + sz * m00i;  g[1] = cz * m00i - sz * m00r;
        g[2] = cz * m01r + sz * m01i;  g[3] = cz * m01i - sz * m01r;
        g[4] = cz * m10r - sz * m10i;  g[5] = cz * m10i + sz * m10r;
        g[6] = cz * m11r - sz * m11i;  g[7] = cz * m11i + sz * m11r;
    }
}

// ---------------------------------------------------------------------------
// W split/transpose: g_wth/g_wtl[n][k] bf16 hi/lo of W1[k][n], zero-padded
// ---------------------------------------------------------------------------
__global__ void wsplit_kernel(const float* __restrict__ W) {
    __shared__ float tile[32][33];
    const int k0 = blockIdx.x * 32;
    const int n0 = blockIdx.y * 32;
    const int tx = threadIdx.x, ty = threadIdx.y;  // 32 x 8
    #pragma unroll
    for (int i = 0; i < 4; i++) {
        const int k = k0 + ty + i * 8;
        tile[ty + i * 8][tx] = (k < K_DIM) ? W[(size_t)k * N1 + n0 + tx] : 0.0f;
    }
    __syncthreads();
    #pragma unroll
    for (int i = 0; i < 4; i++) {
        const int n = n0 + ty + i * 8;
        const float v = tile[tx][ty + i * 8];
        const __nv_bfloat16 h = __float2bfloat16(v);
        const float lo = v - __bfloat162float(h);
        g_wth[(size_t)n * KPAD + k0 + tx] = h;
        g_wtl[(size_t)n * KPAD + k0 + tx] = __float2bfloat16(lo);
    }
}

// ---------------------------------------------------------------------------
// X split: g_xh/g_xl[m][k] bf16 hi/lo, zero-padded to KPAD (streaming)
// ---------------------------------------------------------------------------
__global__ __launch_bounds__(256) void xsplit_kernel(const float* __restrict__ X) {
    const int m = blockIdx.x;
    const float4* src = (const float4*)(X + (size_t)m * K_DIM);
    uint2* oh = (uint2*)(g_xh + (size_t)m * KPAD);
    uint2* ol = (uint2*)(g_xl + (size_t)m * KPAD);
    for (int i = threadIdx.x; i < KPAD / 4; i += 256) {
        float4 v = (i < K_DIM / 4) ? src[i] : make_float4(0.f, 0.f, 0.f, 0.f);
        const uint32_t h01 = packbf(v.x, v.y);
        const uint32_t h23 = packbf(v.z, v.w);
        const uint32_t l01 = packlo(h01, v.x, v.y);
        const uint32_t l23 = packlo(h23, v.z, v.w);
        oh[i] = make_uint2(h01, h23);
        ol[i] = make_uint2(l01, l23);
    }
}

// ---------------------------------------------------------------------------
// GEMM1 via HMMA bf16 3-term, pure ldsm+mma mainloop
// CTA 128x128, KC=64, 512 threads (16 warps, 4m x 4n), warp tile 32x32
// ---------------------------------------------------------------------------
__global__ __launch_bounds__(512, 1)
void gemm1_hmma_kernel(const float* __restrict__ bias)
{
    extern __shared__ char smraw[];
    const uint32_t sb = smem_u32(smraw);

    const int tid  = threadIdx.x;
    const int lane = tid & 31;
    const int wid  = tid >> 5;
    const int wm   = wid >> 2;       // 0..3
    const int wn   = wid & 3;        // 0..3
    const int m0   = blockIdx.y * 128;
    const int n0   = blockIdx.x * 128;

    // cp.async geometry: idx = tid + 512*j (j<2): row = idx>>3, g = idx&7
    const int r0_ = tid >> 3, g0_ = tid & 7;
    const int r1_ = (tid + 512) >> 3, g1_ = (tid + 512) & 7;
    const uint32_t d0 = swz(r0_ * 128 + g0_ * 16);
    const uint32_t d1 = swz(r1_ * 128 + g1_ * 16);
    // explicit per-array source pointers (NO shared offsets across arrays!)
    const __nv_bfloat16* ah0 = g_xh  + (size_t)(m0 + r0_) * KPAD + g0_ * 8;
    const __nv_bfloat16* ah1 = g_xh  + (size_t)(m0 + r1_) * KPAD + g1_ * 8;
    const __nv_bfloat16* al0 = g_xl  + (size_t)(m0 + r0_) * KPAD + g0_ * 8;
    const __nv_bfloat16* al1 = g_xl  + (size_t)(m0 + r1_) * KPAD + g1_ * 8;
    const __nv_bfloat16* bh0 = g_wth + (size_t)(n0 + r0_) * KPAD + g0_ * 8;
    const __nv_bfloat16* bh1 = g_wth + (size_t)(n0 + r1_) * KPAD + g1_ * 8;
    const __nv_bfloat16* bl0 = g_wtl + (size_t)(n0 + r0_) * KPAD + g0_ * 8;
    const __nv_bfloat16* bl1 = g_wtl + (size_t)(n0 + r1_) * KPAD + g1_ * 8;

    #define ISSUE(kb, buf) do {                                                \
        const uint32_t bo = sb + (buf) * BUF;                                  \
        cpasync16(bo + d0,             ah0 + (kb));                            \
        cpasync16(bo + d1,             ah1 + (kb));                            \
        cpasync16(bo + ATILE + d0,     al0 + (kb));                            \
        cpasync16(bo + ATILE + d1,     al1 + (kb));                            \
        cpasync16(bo + 2 * ATILE + d0, bh0 + (kb));                            \
        cpasync16(bo + 2 * ATILE + d1, bh1 + (kb));                            \
        cpasync16(bo + 3 * ATILE + d0, bl0 + (kb));                            \
        cpasync16(bo + 3 * ATILE + d1, bl1 + (kb));                            \
        cp_commit();                                                           \
    } while (0)

    float acc[2][4][4];
    #pragma unroll
    for (int i = 0; i < 2; i++)
        #pragma unroll
        for (int j = 0; j < 4; j++)
            #pragma unroll
            for (int c = 0; c < 4; c++) acc[i][j][c] = 0.0f;

    // ldsm lane addressing (bf16: 16 elems = 32B per k-step; halves at +16B)
    const int arow = lane & 15;
    const int akoff = (lane >> 4) * 16;
    const int brow = (lane & 7) + ((lane >> 4) << 3);
    const int bkoff = ((lane >> 3) & 1) * 16;

    ISSUE(0, 0);

    for (int t = 0; t < NCH; t++) {
        const int buf = t & 1;
        if (t + 1 < NCH) { ISSUE((size_t)(t + 1) * KC, buf ^ 1); cp_wait1(); }
        else cp_wait0();
        __syncthreads();

        const uint32_t ab = sb + buf * BUF;
        const uint32_t bb = ab + 2 * ATILE;

        #pragma unroll
        for (int ks = 0; ks < 4; ks++) {
            uint32_t ah[2][4], al[2][4], bh[2][4], bl[2][4];
            #pragma unroll
            for (int mt = 0; mt < 2; mt++) {
                const uint32_t ad = ab + swz((wm * 32 + mt * 16 + arow) * 128
                                             + ks * 32 + akoff);
                ldsm4(ah[mt], ad);
                ldsm4(al[mt], ad + ATILE);
            }
            #pragma unroll
            for (int p = 0; p < 2; p++) {
                const uint32_t bd = bb + swz((wn * 32 + p * 16 + brow) * 128
                                             + ks * 32 + bkoff);
                ldsm4(bh[p], bd);
                ldsm4(bl[p], bd + ATILE);
            }
            // term 1: hi*hi
            #pragma unroll
            for (int mt = 0; mt < 2; mt++)
                #pragma unroll
                for (int p = 0; p < 2; p++)
                    #pragma unroll
                    for (int h = 0; h < 2; h++)
                        mma_bf16(acc[mt][p * 2 + h], ah[mt],
                                 bh[p][2 * h], bh[p][2 * h + 1]);
            // term 2: lo*hi
            #pragma unroll
            for (int mt = 0; mt < 2; mt++)
                #pragma unroll
                for (int p = 0; p < 2; p++)
                    #pragma unroll
                    for (int h = 0; h < 2; h++)
                        mma_bf16(acc[mt][p * 2 + h], al[mt],
                                 bh[p][2 * h], bh[p][2 * h + 1]);
            // term 3: hi*lo
            #pragma unroll
            for (int mt = 0; mt < 2; mt++)
                #pragma unroll
                for (int p = 0; p < 2; p++)
                    #pragma unroll
                    for (int h = 0; h < 2; h++)
                        mma_bf16(acc[mt][p * 2 + h], ah[mt],
                                 bl[p][2 * h], bl[p][2 * h + 1]);
        }
        __syncthreads();
    }

    // epilogue: bias + relu
    const int fr = lane >> 2;
    const int fc = (lane & 3) * 2;
    #pragma unroll
    for (int nt = 0; nt < 4; nt++) {
        const int c = n0 + wn * 32 + nt * 8 + fc;
        const float b0 = bias[c], b1 = bias[c + 1];
        #pragma unroll
        for (int mt = 0; mt < 2; mt++) {
            const int r = m0 + wm * 32 + mt * 16 + fr;
            float2 o0, o1;
            o0.x = fmaxf(acc[mt][nt][0] + b0, 0.f);
            o0.y = fmaxf(acc[mt][nt][1] + b1, 0.f);
            o1.x = fmaxf(acc[mt][nt][2] + b0, 0.f);
            o1.y = fmaxf(acc[mt][nt][3] + b1, 0.f);
            *(float2*)&g_h[(size_t)r * N1 + c] = o0;
            *(float2*)&g_h[(size_t)(r + 8) * N1 + c] = o1;
        }
    }
    #undef ISSUE
}

// ---------------------------------------------------------------------------
// Fused tail: angles -> 8-qubit sim (fused U gates) -> post-MLP
// ---------------------------------------------------------------------------
__device__ __forceinline__ float bsum(float v) {
    #pragma unroll
    for (int m = 16; m > 0; m >>= 1) v += __shfl_xor_sync(0xffffffffu, v, m);
    return v;
}

__global__ __launch_bounds__(256) void tail_kernel(
    const float* __restrict__ preW2, const float* __restrict__ preb2,
    const float* __restrict__ pW1, const float* __restrict__ pb1,
    const float* __restrict__ pW2, const float* __restrict__ pb2,
    const float* __restrict__ pW3, const float* __restrict__ pb3,
    float* __restrict__ out)
{
    __shared__ float sh[8][128];
    __shared__ float w2s[128 * 64];

    const int lane = threadIdx.x & 31;
    const int w    = threadIdx.x >> 5;
    const int sample = blockIdx.x * 8 + w;

    for (int i = threadIdx.x; i < (128 * 64) / 4; i += 256)
        ((float4*)w2s)[i] = ((const float4*)pW2)[i];
    __syncthreads();

    const float* hrow = g_h + (size_t)sample * N1;
    float acc[8] = {0, 0, 0, 0, 0, 0, 0, 0};
    #pragma unroll
    for (int t = 0; t < 16; t++) {
        const int k = t * 32 + lane;
        const float hv = hrow[k];
        const float4 wa = *(const float4*)(preW2 + (size_t)k * FEAT);
        const float4 wb = *(const float4*)(preW2 + (size_t)k * FEAT + 4);
        acc[0] = fmaf(hv, wa.x, acc[0]); acc[1] = fmaf(hv, wa.y, acc[1]);
        acc[2] = fmaf(hv, wa.z, acc[2]); acc[3] = fmaf(hv, wa.w, acc[3]);
        acc[4] = fmaf(hv, wb.x, acc[4]); acc[5] = fmaf(hv, wb.y, acc[5]);
        acc[6] = fmaf(hv, wb.z, acc[6]); acc[7] = fmaf(hv, wb.w, acc[7]);
    }

    float v0[8], v1[8];
    #pragma unroll
    for (int q = 0; q < 8; q++) {
        const float s_ = bsum(acc[q]);
        const float th = tanhf(s_ + preb2[q]) * 1.57079632679f;
        float c, s;
        sincosf(th, &s, &c);
        v0[q] = (c - s) * 0.70710678118f;
        v1[q] = (c + s) * 0.70710678118f;
    }
    float re[8], im[8];
    #pragma unroll
    for (int j = 0; j < 8; j++) {
        const int g = (lane << 3) | j;
        float a = 1.0f;
        #pragma unroll
        for (int q = 0; q < 8; q++)
            a *= ((g >> (7 - q)) & 1) ? v1[q] : v0[q];
        re[j] = a; im[j] = 0.0f;
    }

    for (int l = 0; l < NL; l++) {
        // CNOT(0,1)
        {
            const int take = (lane >> 4) & 1;
            #pragma unroll
            for (int j = 0; j < 8; j++) {
                const float orr = __shfl_xor_sync(~0u, re[j], 8);
                const float oii = __shfl_xor_sync(~0u, im[j], 8);
                if (take) { re[j] = orr; im[j] = oii; }
            }
        }
        // CNOT(2,3)
        {
            const int take = (lane >> 2) & 1;
            #pragma unroll
            for (int j = 0; j < 8; j++) {
                const float orr = __shfl_xor_sync(~0u, re[j], 2);
                const float oii = __shfl_xor_sync(~0u, im[j], 2);
                if (take) { re[j] = orr; im[j] = oii; }
            }
        }
        // CNOT(4,5)
        if (lane & 1) {
            #pragma unroll
            for (int j = 0; j < 4; j++) {
                float t = re[j]; re[j] = re[j + 4]; re[j + 4] = t;
                t = im[j]; im[j] = im[j + 4]; im[j + 4] = t;
            }
        }
        // CNOT(6,7)
        {
            float t;
            t = re[2]; re[2] = re[3]; re[3] = t;  t = im[2]; im[2] = im[3]; im[3] = t;
            t = re[6]; re[6] = re[7]; re[7] = t;  t = im[6]; im[6] = im[7]; im[7] = t;
        }
        // CNOT(1,2)
        {
            const int take = (lane >> 3) & 1;
            #pragma unroll
            for (int j = 0; j < 8; j++) {
                const float orr = __shfl_xor_sync(~0u, re[j], 4);
                const float oii = __shfl_xor_sync(~0u, im[j], 4);
                if (take) { re[j] = orr; im[j] = oii; }
            }
        }
        // CNOT(3,4)
        {
            const int take = (lane >> 1) & 1;
            #pragma unroll
            for (int j = 0; j < 8; j++) {
                const float orr = __shfl_xor_sync(~0u, re[j], 1);
                const float oii = __shfl_xor_sync(~0u, im[j], 1);
                if (take) { re[j] = orr; im[j] = oii; }
            }
        }
        // CNOT(5,6)
        {
            float t;
            t = re[4]; re[4] = re[6]; re[6] = t;  t = im[4]; im[4] = im[6]; im[6] = t;
            t = re[5]; re[5] = re[7]; re[7] = t;  t = im[5]; im[5] = im[7]; im[7] = t;
        }

        // fused U per qubit
        #pragma unroll
        for (int q = 0; q < 8; q++) {
            const float* gg = g_gate + (l * 8 + q) * 8;
            if (q < 5) {
                const int M = 1 << (4 - q);
                const int bit = (lane >> (4 - q)) & 1;
                const float uar = bit ? gg[4] : gg[0];
                const float uai = bit ? gg[5] : gg[1];
                const float ubr = bit ? gg[6] : gg[2];
                const float ubi = bit ? gg[7] : gg[3];
                #pragma unroll
                for (int j = 0; j < 8; j++) {
                    const float orr = __shfl_xor_sync(~0u, re[j], M);
                    const float oii = __shfl_xor_sync(~0u, im[j], M);
                    const float a0r = bit ? orr : re[j];
                    const float a0i = bit ? oii : im[j];
                    const float a1r = bit ? re[j] : orr;
                    const float a1i = bit ? im[j] : oii;
                    re[j] = uar * a0r - uai * a0i + ubr * a1r - ubi * a1i;
                    im[j] = uar * a0i + uai * a0r + ubr * a1i + ubi * a1r;
                }
            } else {
                const int S = 1 << (7 - q);
                const float u00r = gg[0], u00i = gg[1], u01r = gg[2], u01i = gg[3];
                const float u10r = gg[4], u10i = gg[5], u11r = gg[6], u11i = gg[7];
                #pragma unroll
                for (int j0 = 0; j0 < 8; j0++) {
                    if (j0 & S) continue;
                    const int j1 = j0 + S;
                    const float r0 = re[j0], i0 = im[j0];
                    const float r1 = re[j1], i1 = im[j1];
                    re[j0] = u00r * r0 - u00i * i0 + u01r * r1 - u01i * i1;
                    im[j0] = u00r * i0 + u00i * r0 + u01r * i1 + u01i * r1;
                    re[j1] = u10r * r0 - u10i * i0 + u11r * r1 - u11i * i1;
                    im[j1] = u10r * i0 + u10i * r0 + u11r * i1 + u11i * r1;
                }
            }
        }
    }

    float ev[8] = {0, 0, 0, 0, 0, 0, 0, 0};
    #pragma unroll
    for (int j = 0; j < 8; j++) {
        const float p = re[j] * re[j] + im[j] * im[j];
        const int g = (lane << 3) | j;
        #pragma unroll
        for (int q = 0; q < 8; q++)
            ev[q] += ((g >> (7 - q)) & 1) ? -p : p;
    }
    #pragma unroll
    for (int q = 0; q < 8; q++) ev[q] = bsum(ev[q]);

    float* shw = sh[w];
    #pragma unroll
    for (int r = 0; r < 4; r++) {
        const int u = r * 32 + lane;
        float s_ = pb1[u];
        #pragma unroll
        for (int q = 0; q < 8; q++)
            s_ = fmaf(ev[q], pW1[q * 128 + u], s_);
        shw[u] = fmaxf(s_, 0.0f);
    }
    __syncwarp();

    float s0 = pb2[2 * lane], s1 = pb2[2 * lane + 1];
    #pragma unroll 4
    for (int u = 0; u < 128; u++) {
        const float hu = shw[u];
        const float2 wv = *(const float2*)&w2s[u * 64 + 2 * lane];
        s0 = fmaf(hu, wv.x, s0);
        s1 = fmaf(hu, wv.y, s1);
    }
    const float h3a = fmaxf(s0, 0.0f);
    const float h3b = fmaxf(s1, 0.0f);
    __syncwarp();
    shw[2 * lane] = h3a;
    shw[2 * lane + 1] = h3b;
    __syncwarp();

    if (lane < 6) {
        float s_ = pb3[lane];
        #pragma unroll 8
        for (int v = 0; v < 64; v++)
            s_ = fmaf(shw[v], pW3[v * 6 + lane], s_);
        out[(size_t)sample * 6 + lane] = s_;
    }
}

// ---------------------------------------------------------------------------
extern "C" void kernel_launch(void* const* d_in, const int* in_sizes, int n_in,
                              void* d_out, int out_size)
{
    const float* x     = (const float*)d_in[0];
    const float* preW1 = (const float*)d_in[1];
    const float* preb1 = (const float*)d_in[2];
    const float* preW2 = (const float*)d_in[3];
    const float* preb2 = (const float*)d_in[4];
    const float* qp    = (const float*)d_in[5];
    const float* pW1   = (const float*)d_in[6];
    const float* pb1   = (const float*)d_in[7];
    const float* pW2   = (const float*)d_in[8];
    const float* pb2   = (const float*)d_in[9];
    const float* pW3   = (const float*)d_in[10];
    const float* pb3   = (const float*)d_in[11];
    float* out = (float*)d_out;

    cudaFuncSetAttribute(gemm1_hmma_kernel,
                         cudaFuncAttributeMaxDynamicSharedMemorySize, GSMEM);

    prep_gates_kernel<<<1, 32>>>(qp);
    wsplit_kernel<<<dim3(KPAD / 32, N1 / 32), dim3(32, 8)>>>(preW1);
    xsplit_kernel<<<B_SAMP, 256>>>(x);

    dim3 gg(N1 / 128, B_SAMP / 128);   // (4, 64)
    gemm1_hmma_kernel<<<gg, 512, GSMEM>>>(preb1);

    tail_kernel<<<B_SAMP / 8, 256>>>(preW2, preb2, pW1, pb1, pW2, pb2,
                                     pW3, pb3, out);
}

// round 15
// speedup vs baseline: 2.7463x; 1.0183x over previous
#include <cuda_runtime.h>
#include <cuda_bf16.h>
#include <stdint.h>
#include <math.h>

#define B_SAMP 8192
#define K_DIM  7056
#define KPAD   7104          // 111 * 64
#define N1     512
#define FEAT   256
#define NQ     8
#define NL     3

#define KC    64
#define NCH   (KPAD / KC)    // 111
// per-stage: Ah 16K | Al 16K | Bh 8K | Bl 8K = 48K; 2 stages = 96K
#define A_T   16384
#define B_T   8192
#define STG   (2 * A_T + 2 * B_T)
#define GSMEM (2 * STG)

// ---------------- device scratch ----------------
__device__ float g_h[(size_t)B_SAMP * N1];
__device__ float g_gate[NL * NQ * 8];                 // fused U = Rz*Ry*Rx
__device__ __nv_bfloat16 g_xh[(size_t)B_SAMP * KPAD];
__device__ __nv_bfloat16 g_xl[(size_t)B_SAMP * KPAD];
__device__ __nv_bfloat16 g_wth[(size_t)N1 * KPAD];    // W1^T hi (K-major)
__device__ __nv_bfloat16 g_wtl[(size_t)N1 * KPAD];

// ---------------- helpers ----------------
__device__ __forceinline__ uint32_t smem_u32(const void* p) {
    uint32_t a;
    asm("{ .reg .u64 t; cvta.to.shared.u64 t, %1; cvt.u32.u64 %0, t; }"
        : "=r"(a) : "l"(p));
    return a;
}
__device__ __forceinline__ void cpasync16(uint32_t dst, const void* src) {
    asm volatile("cp.async.cg.shared.global [%0], [%1], 16;"
                 :: "r"(dst), "l"(src) : "memory");
}
__device__ __forceinline__ void cp_commit() {
    asm volatile("cp.async.commit_group;" ::: "memory");
}
__device__ __forceinline__ void cp_wait1() {
    asm volatile("cp.async.wait_group 1;" ::: "memory");
}
__device__ __forceinline__ void cp_wait0() {
    asm volatile("cp.async.wait_group 0;" ::: "memory");
}
__device__ __forceinline__ void ldsm4(uint32_t* r, uint32_t addr) {
    asm volatile("ldmatrix.sync.aligned.m8n8.x4.shared.b16 {%0,%1,%2,%3}, [%4];"
                 : "=r"(r[0]), "=r"(r[1]), "=r"(r[2]), "=r"(r[3]) : "r"(addr));
}
__device__ __forceinline__ void mma_bf16(float* d, const uint32_t* a,
                                         uint32_t b0, uint32_t b1) {
    asm volatile(
        "mma.sync.aligned.m16n8k16.row.col.f32.bf16.bf16.f32 "
        "{%0,%1,%2,%3},{%4,%5,%6,%7},{%8,%9},{%0,%1,%2,%3};"
        : "+f"(d[0]), "+f"(d[1]), "+f"(d[2]), "+f"(d[3])
        : "r"(a[0]), "r"(a[1]), "r"(a[2]), "r"(a[3]), "r"(b0), "r"(b1));
}
__device__ __forceinline__ uint32_t swz(uint32_t off) {   // 128B rows
    return off ^ (((off >> 7) & 7) << 4);
}
__device__ __forceinline__ uint32_t packbf(float e0, float e1) {
    uint32_t r;
    asm("cvt.rn.bf16x2.f32 %0, %1, %2;" : "=r"(r) : "f"(e1), "f"(e0));
    return r;
}
__device__ __forceinline__ uint32_t packlo(uint32_t hpair, float e0, float e1) {
    float h0 = __uint_as_float(hpair << 16);
    float h1 = __uint_as_float(hpair & 0xFFFF0000u);
    return packbf(e0 - h0, e1 - h1);
}

// ---------------------------------------------------------------------------
// Fused gate precompute
// ---------------------------------------------------------------------------
__global__ void prep_gates_kernel(const float* __restrict__ qp) {
    int p = threadIdx.x;
    if (p < NL * NQ) {
        float cx, sx, cy, sy, cz, sz;
        sincosf(0.5f * qp[p * 3 + 0], &sx, &cx);
        sincosf(0.5f * qp[p * 3 + 1], &sy, &cy);
        sincosf(0.5f * qp[p * 3 + 2], &sz, &cz);
        const float m00r = cy * cx, m00i =  sy * sx;
        const float m01r = -sy * cx, m01i = -cy * sx;
        const float m10r =  sy * cx, m10i = -cy * sx;
        const float m11r =  cy * cx, m11i = -sy * sx;
        float* g = g_gate + p * 8;
        g[0] = cz * m00r + sz * m00i;  g[1] = cz * m00i - sz * m00r;
        g[2] = cz * m01r + sz * m01i;  g[3] = cz * m01i - sz * m01r;
        g[4] = cz * m10r - sz * m10i;  g[5] = cz * m10i + sz * m10r;
        g[6] = cz * m11r - sz * m11i;  g[7] = cz * m11i + sz * m11r;
    }
}

// ---------------------------------------------------------------------------
// W split/transpose
// ---------------------------------------------------------------------------
__global__ void wsplit_kernel(const float* __restrict__ W) {
    __shared__ float tile[32][33];
    const int k0 = blockIdx.x * 32;
    const int n0 = blockIdx.y * 32;
    const int tx = threadIdx.x, ty = threadIdx.y;  // 32 x 8
    #pragma unroll
    for (int i = 0; i < 4; i++) {
        const int k = k0 + ty + i * 8;
        tile[ty + i * 8][tx] = (k < K_DIM) ? W[(size_t)k * N1 + n0 + tx] : 0.0f;
    }
    __syncthreads();
    #pragma unroll
    for (int i = 0; i < 4; i++) {
        const int n = n0 + ty + i * 8;
        const float v = tile[tx][ty + i * 8];
        const __nv_bfloat16 h = __float2bfloat16(v);
        const float lo = v - __bfloat162float(h);
        g_wth[(size_t)n * KPAD + k0 + tx] = h;
        g_wtl[(size_t)n * KPAD + k0 + tx] = __float2bfloat16(lo);
    }
}

// ---------------------------------------------------------------------------
// X split (streaming)
// ---------------------------------------------------------------------------
__global__ __launch_bounds__(256) void xsplit_kernel(const float* __restrict__ X) {
    const int m = blockIdx.x;
    const float4* src = (const float4*)(X + (size_t)m * K_DIM);
    uint2* oh = (uint2*)(g_xh + (size_t)m * KPAD);
    uint2* ol = (uint2*)(g_xl + (size_t)m * KPAD);
    for (int i = threadIdx.x; i < KPAD / 4; i += 256) {
        float4 v = (i < K_DIM / 4) ? src[i] : make_float4(0.f, 0.f, 0.f, 0.f);
        const uint32_t h01 = packbf(v.x, v.y);
        const uint32_t h23 = packbf(v.z, v.w);
        const uint32_t l01 = packlo(h01, v.x, v.y);
        const uint32_t l23 = packlo(h23, v.z, v.w);
        oh[i] = make_uint2(h01, h23);
        ol[i] = make_uint2(l01, l23);
    }
}

// ---------------------------------------------------------------------------
// GEMM1 via HMMA bf16 3-term
// CTA tile 128x64, KC=64, 256 threads (8 warps, 4m x 2n), warp tile 32x32
// 2 CTAs/SM -> independent barrier domains keep tensor pipe fed
// ---------------------------------------------------------------------------
__global__ __launch_bounds__(256, 2)
void gemm1_hmma_kernel(const float* __restrict__ bias)
{
    extern __shared__ char smraw[];
    const uint32_t sb = smem_u32(smraw);

    const int tid  = threadIdx.x;
    const int lane = tid & 31;
    const int wid  = tid >> 5;
    const int wm   = wid >> 1;       // 0..3 -> m offset 32*wm
    const int wn   = wid & 1;        // 0..1 -> n offset 32*wn
    const int m0   = blockIdx.y * 128;
    const int n0   = blockIdx.x * 64;

    // loader geometry: r0 = tid>>3 (0..31), g0 = tid&7 (16B chunk)
    // A rows r0+32j (j<4), B rows r0+32j (j<2); g/d-offset invariant mod 32 rows
    const int r0 = tid >> 3, g0 = tid & 7;
    const uint32_t d0 = swz(r0 * 128 + g0 * 16);
    const __nv_bfloat16* ahb = g_xh  + (size_t)(m0 + r0) * KPAD + g0 * 8;
    const __nv_bfloat16* alb = g_xl  + (size_t)(m0 + r0) * KPAD + g0 * 8;
    const __nv_bfloat16* bhb = g_wth + (size_t)(n0 + r0) * KPAD + g0 * 8;
    const __nv_bfloat16* blb = g_wtl + (size_t)(n0 + r0) * KPAD + g0 * 8;
    const size_t RSTEP = (size_t)32 * KPAD;

    #define ISSUE(kb, buf) do {                                                \
        const uint32_t bo = sb + (buf) * STG;                                  \
        _Pragma("unroll")                                                      \
        for (int j = 0; j < 4; j++) {                                          \
            cpasync16(bo + d0 + 4096 * j,       ahb + j * RSTEP + (kb));       \
            cpasync16(bo + A_T + d0 + 4096 * j, alb + j * RSTEP + (kb));       \
        }                                                                      \
        _Pragma("unroll")                                                      \
        for (int j = 0; j < 2; j++) {                                          \
            cpasync16(bo + 2 * A_T + d0 + 4096 * j,       bhb + j * RSTEP + (kb)); \
            cpasync16(bo + 2 * A_T + B_T + d0 + 4096 * j, blb + j * RSTEP + (kb)); \
        }                                                                      \
        cp_commit();                                                           \
    } while (0)

    float acc[2][4][4];
    #pragma unroll
    for (int i = 0; i < 2; i++)
        #pragma unroll
        for (int j = 0; j < 4; j++)
            #pragma unroll
            for (int c = 0; c < 4; c++) acc[i][j][c] = 0.0f;

    // ldsm lane addressing
    const int arow = lane & 15;
    const int akoff = (lane >> 4) * 16;
    const int brow = (lane & 7) + ((lane >> 4) << 3);
    const int bkoff = ((lane >> 3) & 1) * 16;

    ISSUE(0, 0);

    for (int t = 0; t < NCH; t++) {
        const int buf = t & 1;
        if (t + 1 < NCH) { ISSUE((size_t)(t + 1) * KC, buf ^ 1); cp_wait1(); }
        else cp_wait0();
        __syncthreads();

        const uint32_t ab = sb + buf * STG;
        const uint32_t bb = ab + 2 * A_T;

        #pragma unroll
        for (int ks = 0; ks < 4; ks++) {
            uint32_t ah[2][4], al[2][4], bh[2][4], bl[2][4];
            #pragma unroll
            for (int mt = 0; mt < 2; mt++) {
                const uint32_t ad = ab + swz((wm * 32 + mt * 16 + arow) * 128
                                             + ks * 32 + akoff);
                ldsm4(ah[mt], ad);
                ldsm4(al[mt], ad + A_T);
            }
            #pragma unroll
            for (int p = 0; p < 2; p++) {
                const uint32_t bd = bb + swz((wn * 32 + p * 16 + brow) * 128
                                             + ks * 32 + bkoff);
                ldsm4(bh[p], bd);
                ldsm4(bl[p], bd + B_T);
            }
            // term 1: hi*hi
            #pragma unroll
            for (int mt = 0; mt < 2; mt++)
                #pragma unroll
                for (int p = 0; p < 2; p++)
                    #pragma unroll
                    for (int h = 0; h < 2; h++)
                        mma_bf16(acc[mt][p * 2 + h], ah[mt],
                                 bh[p][2 * h], bh[p][2 * h + 1]);
            // term 2: lo*hi
            #pragma unroll
            for (int mt = 0; mt < 2; mt++)
                #pragma unroll
                for (int p = 0; p < 2; p++)
                    #pragma unroll
                    for (int h = 0; h < 2; h++)
                        mma_bf16(acc[mt][p * 2 + h], al[mt],
                                 bh[p][2 * h], bh[p][2 * h + 1]);
            // term 3: hi*lo
            #pragma unroll
            for (int mt = 0; mt < 2; mt++)
                #pragma unroll
                for (int p = 0; p < 2; p++)
                    #pragma unroll
                    for (int h = 0; h < 2; h++)
                        mma_bf16(acc[mt][p * 2 + h], ah[mt],
                                 bl[p][2 * h], bl[p][2 * h + 1]);
        }
        __syncthreads();
    }

    // epilogue: bias + relu
    const int fr = lane >> 2;
    const int fc = (lane & 3) * 2;
    #pragma unroll
    for (int nt = 0; nt < 4; nt++) {
        const int c = n0 + wn * 32 + nt * 8 + fc;
        const float b0 = bias[c], b1 = bias[c + 1];
        #pragma unroll
        for (int mt = 0; mt < 2; mt++) {
            const int r = m0 + wm * 32 + mt * 16 + fr;
            float2 o0, o1;
            o0.x = fmaxf(acc[mt][nt][0] + b0, 0.f);
            o0.y = fmaxf(acc[mt][nt][1] + b1, 0.f);
            o1.x = fmaxf(acc[mt][nt][2] + b0, 0.f);
            o1.y = fmaxf(acc[mt][nt][3] + b1, 0.f);
            *(float2*)&g_h[(size_t)r * N1 + c] = o0;
            *(float2*)&g_h[(size_t)(r + 8) * N1 + c] = o1;
        }
    }
    #undef ISSUE
}

// ---------------------------------------------------------------------------
// Fused tail: angles -> 8-qubit sim (fused U gates) -> post-MLP
// ---------------------------------------------------------------------------
__device__ __forceinline__ float bsum(float v) {
    #pragma unroll
    for (int m = 16; m > 0; m >>= 1) v += __shfl_xor_sync(0xffffffffu, v, m);
    return v;
}

__global__ __launch_bounds__(256) void tail_kernel(
    const float* __restrict__ preW2, const float* __restrict__ preb2,
    const float* __restrict__ pW1, const float* __restrict__ pb1,
    const float* __restrict__ pW2, const float* __restrict__ pb2,
    const float* __restrict__ pW3, const float* __restrict__ pb3,
    float* __restrict__ out)
{
    __shared__ float sh[8][128];
    __shared__ float w2s[128 * 64];

    const int lane = threadIdx.x & 31;
    const int w    = threadIdx.x >> 5;
    const int sample = blockIdx.x * 8 + w;

    for (int i = threadIdx.x; i < (128 * 64) / 4; i += 256)
        ((float4*)w2s)[i] = ((const float4*)pW2)[i];
    __syncthreads();

    const float* hrow = g_h + (size_t)sample * N1;
    float acc[8] = {0, 0, 0, 0, 0, 0, 0, 0};
    #pragma unroll
    for (int t = 0; t < 16; t++) {
        const int k = t * 32 + lane;
        const float hv = hrow[k];
        const float4 wa = *(const float4*)(preW2 + (size_t)k * FEAT);
        const float4 wb = *(const float4*)(preW2 + (size_t)k * FEAT + 4);
        acc[0] = fmaf(hv, wa.x, acc[0]); acc[1] = fmaf(hv, wa.y, acc[1]);
        acc[2] = fmaf(hv, wa.z, acc[2]); acc[3] = fmaf(hv, wa.w, acc[3]);
        acc[4] = fmaf(hv, wb.x, acc[4]); acc[5] = fmaf(hv, wb.y, acc[5]);
        acc[6] = fmaf(hv, wb.z, acc[6]); acc[7] = fmaf(hv, wb.w, acc[7]);
    }

    float v0[8], v1[8];
    #pragma unroll
    for (int q = 0; q < 8; q++) {
        const float s_ = bsum(acc[q]);
        const float th = tanhf(s_ + preb2[q]) * 1.57079632679f;
        float c, s;
        sincosf(th, &s, &c);
        v0[q] = (c - s) * 0.70710678118f;
        v1[q] = (c + s) * 0.70710678118f;
    }
    float re[8], im[8];
    #pragma unroll
    for (int j = 0; j < 8; j++) {
        const int g = (lane << 3) | j;
        float a = 1.0f;
        #pragma unroll
        for (int q = 0; q < 8; q++)
            a *= ((g >> (7 - q)) & 1) ? v1[q] : v0[q];
        re[j] = a; im[j] = 0.0f;
    }

    for (int l = 0; l < NL; l++) {
        // CNOT(0,1)
        {
            const int take = (lane >> 4) & 1;
            #pragma unroll
            for (int j = 0; j < 8; j++) {
                const float orr = __shfl_xor_sync(~0u, re[j], 8);
                const float oii = __shfl_xor_sync(~0u, im[j], 8);
                if (take) { re[j] = orr; im[j] = oii; }
            }
        }
        // CNOT(2,3)
        {
            const int take = (lane >> 2) & 1;
            #pragma unroll
            for (int j = 0; j < 8; j++) {
                const float orr = __shfl_xor_sync(~0u, re[j], 2);
                const float oii = __shfl_xor_sync(~0u, im[j], 2);
                if (take) { re[j] = orr; im[j] = oii; }
            }
        }
        // CNOT(4,5)
        if (lane & 1) {
            #pragma unroll
            for (int j = 0; j < 4; j++) {
                float t = re[j]; re[j] = re[j + 4]; re[j + 4] = t;
                t = im[j]; im[j] = im[j + 4]; im[j + 4] = t;
            }
        }
        // CNOT(6,7)
        {
            float t;
            t = re[2]; re[2] = re[3]; re[3] = t;  t = im[2]; im[2] = im[3]; im[3] = t;
            t = re[6]; re[6] = re[7]; re[7] = t;  t = im[6]; im[6] = im[7]; im[7] = t;
        }
        // CNOT(1,2)
        {
            const int take = (lane >> 3) & 1;
            #pragma unroll
            for (int j = 0; j < 8; j++) {
                const float orr = __shfl_xor_sync(~0u, re[j], 4);
                const float oii = __shfl_xor_sync(~0u, im[j], 4);
                if (take) { re[j] = orr; im[j] = oii; }
            }
        }
        // CNOT(3,4)
        {
            const int take = (lane >> 1) & 1;
            #pragma unroll
            for (int j = 0; j < 8; j++) {
                const float orr = __shfl_xor_sync(~0u, re[j], 1);
                const float oii = __shfl_xor_sync(~0u, im[j], 1);
                if (take) { re[j] = orr; im[j] = oii; }
            }
        }
        // CNOT(5,6)
        {
            float t;
            t = re[4]; re[4] = re[6]; re[6] = t;  t = im[4]; im[4] = im[6]; im[6] = t;
            t = re[5]; re[5] = re[7]; re[7] = t;  t = im[5]; im[5] = im[7]; im[7] = t;
        }

        // fused U per qubit
        #pragma unroll
        for (int q = 0; q < 8; q++) {
            const float* gg = g_gate + (l * 8 + q) * 8;
            if (q < 5) {
                const int M = 1 << (4 - q);
                const int bit = (lane >> (4 - q)) & 1;
                const float uar = bit ? gg[4] : gg[0];
                const float uai = bit ? gg[5] : gg[1];
                const float ubr = bit ? gg[6] : gg[2];
                const float ubi = bit ? gg[7] : gg[3];
                #pragma unroll
                for (int j = 0; j < 8; j++) {
                    const float orr = __shfl_xor_sync(~0u, re[j], M);
                    const float oii = __shfl_xor_sync(~0u, im[j], M);
                    const float a0r = bit ? orr : re[j];
                    const float a0i = bit ? oii : im[j];
                    const float a1r = bit ? re[j] : orr;
                    const float a1i = bit ? im[j] : oii;
                    re[j] = uar * a0r - uai * a0i + ubr * a1r - ubi * a1i;
                    im[j] = uar * a0i + uai * a0r + ubr * a1i + ubi * a1r;
                }
            } else {
                const int S = 1 << (7 - q);
                const float u00r = gg[0], u00i = gg[1], u01r = gg[2], u01i = gg[3];
                const float u10r = gg[4], u10i = gg[5], u11r = gg[6], u11i = gg[7];
                #pragma unroll
                for (int j0 = 0; j0 < 8; j0++) {
                    if (j0 & S) continue;
                    const int j1 = j0 + S;
                    const float r0 = re[j0], i0 = im[j0];
                    const float r1 = re[j1], i1 = im[j1];
                    re[j0] = u00r * r0 - u00i * i0 + u01r * r1 - u01i * i1;
                    im[j0] = u00r * i0 + u00i * r0 + u01r * i1 + u01i * r1;
                    re[j1] = u10r * r0 - u10i * i0 + u11r * r1 - u11i * i1;
                    im[j1] = u10r * i0 + u10i * r0 + u11r * i1 + u11i * r1;
                }
            }
        }
    }

    float ev[8] = {0, 0, 0, 0, 0, 0, 0, 0};
    #pragma unroll
    for (int j = 0; j < 8; j++) {
        const float p = re[j] * re[j] + im[j] * im[j];
        const int g = (lane << 3) | j;
        #pragma unroll
        for (int q = 0; q < 8; q++)
            ev[q] += ((g >> (7 - q)) & 1) ? -p : p;
    }
    #pragma unroll
    for (int q = 0; q < 8; q++) ev[q] = bsum(ev[q]);

    float* shw = sh[w];
    #pragma unroll
    for (int r = 0; r < 4; r++) {
        const int u = r * 32 + lane;
        float s_ = pb1[u];
        #pragma unroll
        for (int q = 0; q < 8; q++)
            s_ = fmaf(ev[q], pW1[q * 128 + u], s_);
        shw[u] = fmaxf(s_, 0.0f);
    }
    __syncwarp();

    float s0 = pb2[2 * lane], s1 = pb2[2 * lane + 1];
    #pragma unroll 4
    for (int u = 0; u < 128; u++) {
        const float hu = shw[u];
        const float2 wv = *(const float2*)&w2s[u * 64 + 2 * lane];
        s0 = fmaf(hu, wv.x, s0);
        s1 = fmaf(hu, wv.y, s1);
    }
    const float h3a = fmaxf(s0, 0.0f);
    const float h3b = fmaxf(s1, 0.0f);
    __syncwarp();
    shw[2 * lane] = h3a;
    shw[2 * lane + 1] = h3b;
    __syncwarp();

    if (lane < 6) {
        float s_ = pb3[lane];
        #pragma unroll 8
        for (int v = 0; v < 64; v++)
            s_ = fmaf(shw[v], pW3[v * 6 + lane], s_);
        out[(size_t)sample * 6 + lane] = s_;
    }
}

// ---------------------------------------------------------------------------
extern "C" void kernel_launch(void* const* d_in, const int* in_sizes, int n_in,
                              void* d_out, int out_size)
{
    const float* x     = (const float*)d_in[0];
    const float* preW1 = (const float*)d_in[1];
    const float* preb1 = (const float*)d_in[2];
    const float* preW2 = (const float*)d_in[3];
    const float* preb2 = (const float*)d_in[4];
    const float* qp    = (const float*)d_in[5];
    const float* pW1   = (const float*)d_in[6];
    const float* pb1   = (const float*)d_in[7];
    const float* pW2   = (const float*)d_in[8];
    const float* pb2   = (const float*)d_in[9];
    const float* pW3   = (const float*)d_in[10];
    const float* pb3   = (const float*)d_in[11];
    float* out = (float*)d_out;

    cudaFuncSetAttribute(gemm1_hmma_kernel,
                         cudaFuncAttributeMaxDynamicSharedMemorySize, GSMEM);

    prep_gates_kernel<<<1, 32>>>(qp);
    wsplit_kernel<<<dim3(KPAD / 32, N1 / 32), dim3(32, 8)>>>(preW1);
    xsplit_kernel<<<B_SAMP, 256>>>(x);

    dim3 gg(N1 / 64, B_SAMP / 128);   // (8, 64) = 512 CTAs
    gemm1_hmma_kernel<<<gg, 256, GSMEM>>>(preb1);

    tail_kernel<<<B_SAMP / 8, 256>>>(preW2, preb2, pW1, pb1, pW2, pb2,
                                     pW3, pb3, out);
}